// round 6
// baseline (speedup 1.0000x reference)
#include <cuda_runtime.h>
#include <cuda_bf16.h>

// BasicLS: per-batch least squares.
// For each b: A = [-x[:,1:4], 1]  (32x4), r = x[:,0].
// out[b] = (A^T A)^{-1} A^T r   (4 floats), via normal equations + Cholesky.
//
// Layout: 4 threads per batch, 8 batches per warp. Each thread front-loads
// ALL 8 of its float4 rows into registers (MLP_p1 = 8, keeps ~16KB/SM of
// DRAM requests in flight), then accumulates the 13 normal-equation sums,
// reduces across the 4-lane group with 2 shfl_xor steps, and lane sub==0
// solves the 4x4 SPD system and writes one float4.

__global__ __launch_bounds__(256)
void basic_ls_kernel(const float4* __restrict__ x,
                     float4* __restrict__ out,
                     int B)
{
    const int tid   = blockIdx.x * blockDim.x + threadIdx.x;
    const int warp  = tid >> 5;
    const int lane  = tid & 31;
    const int group = lane >> 2;   // batch within warp (0..7)
    const int sub   = lane & 3;    // row-group within batch (0..3)
    const int batch = warp * 8 + group;
    if (batch >= B) return;

    const float4* __restrict__ base = x + (size_t)batch * 32 + sub;

    // ---- Front-batched loads: 8 independent LDG.128 before ANY math. ----
    float4 v[8];
#pragma unroll
    for (int k = 0; k < 8; ++k)
        v[k] = __ldg(base + k * 4);

    // ---- Accumulate normal-equation sums over this thread's 8 rows. ----
    float sx1 = 0.f, sx2 = 0.f, sx3 = 0.f, sr = 0.f;
    float s11 = 0.f, s12 = 0.f, s13 = 0.f;
    float s22 = 0.f, s23 = 0.f, s33 = 0.f;
    float t1  = 0.f, t2  = 0.f, t3  = 0.f;

#pragma unroll
    for (int k = 0; k < 8; ++k) {
        const float r = v[k].x, a = v[k].y, b = v[k].z, c = v[k].w;
        sx1 += a;  sx2 += b;  sx3 += c;  sr += r;
        s11 = fmaf(a, a, s11);
        s12 = fmaf(a, b, s12);
        s13 = fmaf(a, c, s13);
        s22 = fmaf(b, b, s22);
        s23 = fmaf(b, c, s23);
        s33 = fmaf(c, c, s33);
        t1  = fmaf(a, r, t1);
        t2  = fmaf(b, r, t2);
        t3  = fmaf(c, r, t3);
    }

    // ---- Reduce the 13 sums across the 4-lane group (xor 1, then 2). ----
#pragma unroll
    for (int off = 1; off <= 2; off <<= 1) {
        sx1 += __shfl_xor_sync(0xffffffffu, sx1, off);
        sx2 += __shfl_xor_sync(0xffffffffu, sx2, off);
        sx3 += __shfl_xor_sync(0xffffffffu, sx3, off);
        sr  += __shfl_xor_sync(0xffffffffu, sr,  off);
        s11 += __shfl_xor_sync(0xffffffffu, s11, off);
        s12 += __shfl_xor_sync(0xffffffffu, s12, off);
        s13 += __shfl_xor_sync(0xffffffffu, s13, off);
        s22 += __shfl_xor_sync(0xffffffffu, s22, off);
        s23 += __shfl_xor_sync(0xffffffffu, s23, off);
        s33 += __shfl_xor_sync(0xffffffffu, s33, off);
        t1  += __shfl_xor_sync(0xffffffffu, t1,  off);
        t2  += __shfl_xor_sync(0xffffffffu, t2,  off);
        t3  += __shfl_xor_sync(0xffffffffu, t3,  off);
    }

    if (sub == 0) {
        // Normal equations with A = [-x1, -x2, -x3, 1]:
        const float g11 = s11, g12 = s12, g13 = s13, g14 = -sx1;
        const float g22 = s22, g23 = s23, g24 = -sx2;
        const float g33 = s33, g34 = -sx3;
        const float g44 = 32.0f;               // M rows, a4 == 1, no padding
        const float b1 = -t1, b2 = -t2, b3 = -t3, b4 = sr;

        // Cholesky G = L L^T
        const float l11 = sqrtf(g11);
        const float i11 = 1.0f / l11;
        const float l21 = g12 * i11;
        const float l31 = g13 * i11;
        const float l41 = g14 * i11;

        const float d22 = g22 - l21 * l21;
        const float l22 = sqrtf(d22);
        const float i22 = 1.0f / l22;
        const float l32 = (g23 - l31 * l21) * i22;
        const float l42 = (g24 - l41 * l21) * i22;

        const float d33 = g33 - l31 * l31 - l32 * l32;
        const float l33 = sqrtf(d33);
        const float i33 = 1.0f / l33;
        const float l43 = (g34 - l41 * l31 - l42 * l32) * i33;

        const float d44 = g44 - l41 * l41 - l42 * l42 - l43 * l43;
        const float i44 = 1.0f / sqrtf(d44);

        // Forward solve L y = b
        const float y1 = b1 * i11;
        const float y2 = (b2 - l21 * y1) * i22;
        const float y3 = (b3 - l31 * y1 - l32 * y2) * i33;
        const float y4 = (b4 - l41 * y1 - l42 * y2 - l43 * y3) * i44;

        // Back solve L^T w = y
        const float w4 = y4 * i44;
        const float w3 = (y3 - l43 * w4) * i33;
        const float w2 = (y2 - l32 * w3 - l42 * w4) * i22;
        const float w1 = (y1 - l21 * w2 - l31 * w3 - l41 * w4) * i11;

        out[batch] = make_float4(w1, w2, w3, w4);
    }
}

extern "C" void kernel_launch(void* const* d_in, const int* in_sizes, int n_in,
                              void* d_out, int out_size)
{
    const float4* x = (const float4*)d_in[0];     // (B, 32, 4) fp32
    float4* out = (float4*)d_out;                 // (B, 4) fp32
    const int B = in_sizes[0] / (32 * 4);         // 262144

    // 4 threads per batch, 256 threads per block -> 64 batches per block.
    const int threads = 256;
    const int blocks = (B * 4 + threads - 1) / threads;
    basic_ls_kernel<<<blocks, threads>>>(x, out, B);
}

// round 7
// speedup vs baseline: 1.1578x; 1.1578x over previous
#include <cuda_runtime.h>
#include <cuda_bf16.h>

// BasicLS: per-batch least squares.
// For each b: A = [-x[:,1:4], 1]  (32x4), r = x[:,0].
// out[b] = (A^T A)^{-1} A^T r   (4 floats), via normal equations + Cholesky.
//
// Layout: 4 threads per batch, 8 batches per warp. Each thread front-loads
// ALL 8 of its float4 rows into registers before any math (MLP_p1 = 8).
// __launch_bounds__(256, 4) caps occupancy at 4 CTAs/SM -> 64-reg budget,
// which is what lets ptxas actually keep the 8 loads live simultaneously
// (at the default full-occupancy 32-reg cap it sinks each load next to its
// FMAs, exposing DRAM latency; measured DRAM stuck at 67%).
// Accumulation consumes v[] in REVERSE order so no load can profitably be
// sunk past the first consume point.

__global__ __launch_bounds__(256, 4)
void basic_ls_kernel(const float4* __restrict__ x,
                     float4* __restrict__ out,
                     int B)
{
    const int tid   = blockIdx.x * blockDim.x + threadIdx.x;
    const int warp  = tid >> 5;
    const int lane  = tid & 31;
    const int group = lane >> 2;   // batch within warp (0..7)
    const int sub   = lane & 3;    // row-group within batch (0..3)
    const int batch = warp * 8 + group;
    if (batch >= B) return;

    const float4* __restrict__ base = x + (size_t)batch * 32 + sub;

    // ---- Front-batched loads: 8 independent LDG.128 before ANY math. ----
    float4 v[8];
#pragma unroll
    for (int k = 0; k < 8; ++k)
        v[k] = __ldg(base + k * 4);

    // ---- Accumulate normal-equation sums (reverse order: first use of the
    //      earliest load comes last, defeating load-sinking). ----
    float sx1 = 0.f, sx2 = 0.f, sx3 = 0.f, sr = 0.f;
    float s11 = 0.f, s12 = 0.f, s13 = 0.f;
    float s22 = 0.f, s23 = 0.f, s33 = 0.f;
    float t1  = 0.f, t2  = 0.f, t3  = 0.f;

#pragma unroll
    for (int k = 7; k >= 0; --k) {
        const float r = v[k].x, a = v[k].y, b = v[k].z, c = v[k].w;
        sx1 += a;  sx2 += b;  sx3 += c;  sr += r;
        s11 = fmaf(a, a, s11);
        s12 = fmaf(a, b, s12);
        s13 = fmaf(a, c, s13);
        s22 = fmaf(b, b, s22);
        s23 = fmaf(b, c, s23);
        s33 = fmaf(c, c, s33);
        t1  = fmaf(a, r, t1);
        t2  = fmaf(b, r, t2);
        t3  = fmaf(c, r, t3);
    }

    // ---- Reduce the 13 sums across the 4-lane group (xor 1, then 2). ----
#pragma unroll
    for (int off = 1; off <= 2; off <<= 1) {
        sx1 += __shfl_xor_sync(0xffffffffu, sx1, off);
        sx2 += __shfl_xor_sync(0xffffffffu, sx2, off);
        sx3 += __shfl_xor_sync(0xffffffffu, sx3, off);
        sr  += __shfl_xor_sync(0xffffffffu, sr,  off);
        s11 += __shfl_xor_sync(0xffffffffu, s11, off);
        s12 += __shfl_xor_sync(0xffffffffu, s12, off);
        s13 += __shfl_xor_sync(0xffffffffu, s13, off);
        s22 += __shfl_xor_sync(0xffffffffu, s22, off);
        s23 += __shfl_xor_sync(0xffffffffu, s23, off);
        s33 += __shfl_xor_sync(0xffffffffu, s33, off);
        t1  += __shfl_xor_sync(0xffffffffu, t1,  off);
        t2  += __shfl_xor_sync(0xffffffffu, t2,  off);
        t3  += __shfl_xor_sync(0xffffffffu, t3,  off);
    }

    if (sub == 0) {
        // Normal equations with A = [-x1, -x2, -x3, 1]:
        const float g11 = s11, g12 = s12, g13 = s13, g14 = -sx1;
        const float g22 = s22, g23 = s23, g24 = -sx2;
        const float g33 = s33, g34 = -sx3;
        const float g44 = 32.0f;               // M rows, a4 == 1, no padding
        const float b1 = -t1, b2 = -t2, b3 = -t3, b4 = sr;

        // Cholesky G = L L^T
        const float l11 = sqrtf(g11);
        const float i11 = 1.0f / l11;
        const float l21 = g12 * i11;
        const float l31 = g13 * i11;
        const float l41 = g14 * i11;

        const float d22 = g22 - l21 * l21;
        const float l22 = sqrtf(d22);
        const float i22 = 1.0f / l22;
        const float l32 = (g23 - l31 * l21) * i22;
        const float l42 = (g24 - l41 * l21) * i22;

        const float d33 = g33 - l31 * l31 - l32 * l32;
        const float l33 = sqrtf(d33);
        const float i33 = 1.0f / l33;
        const float l43 = (g34 - l41 * l31 - l42 * l32) * i33;

        const float d44 = g44 - l41 * l41 - l42 * l42 - l43 * l43;
        const float i44 = 1.0f / sqrtf(d44);

        // Forward solve L y = b
        const float y1 = b1 * i11;
        const float y2 = (b2 - l21 * y1) * i22;
        const float y3 = (b3 - l31 * y1 - l32 * y2) * i33;
        const float y4 = (b4 - l41 * y1 - l42 * y2 - l43 * y3) * i44;

        // Back solve L^T w = y
        const float w4 = y4 * i44;
        const float w3 = (y3 - l43 * w4) * i33;
        const float w2 = (y2 - l32 * w3 - l42 * w4) * i22;
        const float w1 = (y1 - l21 * w2 - l31 * w3 - l41 * w4) * i11;

        out[batch] = make_float4(w1, w2, w3, w4);
    }
}

extern "C" void kernel_launch(void* const* d_in, const int* in_sizes, int n_in,
                              void* d_out, int out_size)
{
    const float4* x = (const float4*)d_in[0];     // (B, 32, 4) fp32
    float4* out = (float4*)d_out;                 // (B, 4) fp32
    const int B = in_sizes[0] / (32 * 4);         // 262144

    // 4 threads per batch, 256 threads per block -> 64 batches per block.
    const int threads = 256;
    const int blocks = (B * 4 + threads - 1) / threads;
    basic_ls_kernel<<<blocks, threads>>>(x, out, B);
}